// round 15
// baseline (speedup 1.0000x reference)
#include <cuda_runtime.h>
#include <cuda_bf16.h>
#include <cuda_fp16.h>
#include <cstdint>
#include <math.h>

#define HDIM 1024
#define IEDIM 256
#define NEXP 8
#define VOCAB 100000
#define TMAX 16384
#define TILE_M 128

// int8 tensors stored with each 16-byte K-group permuted:
// [x0 x1 x8 x9 | x2 x3 x10 x11 | x4 x5 x12 x13 | x6 x7 x14 x15]
// A and B share the permutation -> mma fragment pairings AND word-wise dp4a exact.
__device__ __align__(16) int8_t g_xq[TMAX * HDIM];
__device__ float  g_xs[TMAX];
__device__ __align__(16) int8_t g_iq[TMAX * IEDIM];
__device__ float  g_is[TMAX];
__device__ __align__(16) float  g_inter[TMAX * IEDIM];
__device__ __align__(16) int8_t g_w1[NEXP * 2 * IEDIM * HDIM]; // [e][512][1024]
__device__ __align__(16) int8_t g_down_t[NEXP * HDIM * IEDIM]; // [e][H][IE]
__device__ int g_eid[TMAX];
__device__ int g_perm[TMAX];
__device__ int g_counts[NEXP];
__device__ int g_cursor[NEXP];
__device__ int g_off[NEXP + 1];
__device__ int g_wtype;

__device__ __host__ __forceinline__ int kperm(int k) {
    int r = k & 15;
    int p = ((r & 7) >> 1) * 4 + ((r >> 3) << 1) + (r & 1);
    return (k & ~15) | p;
}

// ---------------- low-level helpers ----------------
__device__ __forceinline__ uint32_t smem_u32(const void* p) {
    return (uint32_t)__cvta_generic_to_shared(p);
}
__device__ __forceinline__ void cp16(void* s, const void* g) {
    asm volatile("cp.async.cg.shared.global [%0], [%1], 16;\n"
                 :: "r"(smem_u32(s)), "l"(g));
}
__device__ __forceinline__ void cp_commit() {
    asm volatile("cp.async.commit_group;\n");
}
template <int N>
__device__ __forceinline__ void cp_wait() {
    asm volatile("cp.async.wait_group %0;\n" :: "n"(N));
}
__device__ __forceinline__ void ldsm_x2(uint32_t* r, uint32_t addr) {
    asm volatile("ldmatrix.sync.aligned.m8n8.x2.shared.b16 {%0,%1}, [%2];"
                 : "=r"(r[0]), "=r"(r[1]) : "r"(addr));
}
__device__ __forceinline__ void mma_f16(float* c, const unsigned* a, const unsigned* b) {
    asm volatile(
        "mma.sync.aligned.m16n8k16.row.col.f32.f16.f16.f32 "
        "{%0,%1,%2,%3},{%4,%5,%6,%7},{%8,%9},{%0,%1,%2,%3};"
        : "+f"(c[0]), "+f"(c[1]), "+f"(c[2]), "+f"(c[3])
        : "r"(a[0]), "r"(a[1]), "r"(a[2]), "r"(a[3]), "r"(b[0]), "r"(b[1]));
}
__device__ __forceinline__ void cvt4(unsigned w, unsigned& lo, unsigned& hi) {
    unsigned t = w ^ 0x80808080u;
    unsigned l = __byte_perm(t, 0x64646464u, 0x5140);
    unsigned h = __byte_perm(t, 0x64646464u, 0x5342);
    unsigned bias = 0x64806480u;
    __half2 lh = __hsub2(*(__half2*)&l, *(__half2*)&bias);
    __half2 hh = __hsub2(*(__half2*)&h, *(__half2*)&bias);
    lo = *(unsigned*)&lh;
    hi = *(unsigned*)&hh;
}
__device__ __forceinline__ float fast_silu_mul(float gv, float uv) {
    float sig = __frcp_rn(1.0f + __expf(-gv));
    return gv * sig * uv;
}
__device__ __forceinline__ int dp4a4(int4 a, int4 b, int acc) {
    acc = __dp4a(a.x, b.x, acc); acc = __dp4a(a.y, b.y, acc);
    acc = __dp4a(a.z, b.z, acc); acc = __dp4a(a.w, b.w, acc);
    return acc;
}

// ---------------- dtype probe + counter reset ----------------
__global__ void detect_reset_kernel(const void* __restrict__ w) {
    int t = threadIdx.x;
    if (t < NEXP) { g_counts[t] = 0; g_cursor[t] = 0; }
    int iv = ((const int*)w)[t];
    bool ok_i32 = (iv >= -128 && iv <= 127);
    float fv = ((const float*)w)[t];
    bool ok_f32 = (fv == rintf(fv) && fabsf(fv) <= 127.0f);
    float bv = __bfloat162float(((const __nv_bfloat16*)w)[t]);
    bool ok_bf16 = (bv == rintf(bv) && fabsf(bv) <= 127.0f);
    int c1 = __syncthreads_count(ok_i32);
    int c2 = __syncthreads_count(ok_f32);
    int c3 = __syncthreads_count(ok_bf16);
    if (t == 0) {
        int wt = 0;
        if      (c1 >= 230) wt = 1;
        else if (c2 >= 230) wt = 2;
        else if (c3 >= 230) wt = 3;
        g_wtype = wt;
    }
}

__device__ __forceinline__ int8_t load_w(const void* __restrict__ src, size_t idx, int wt) {
    switch (wt) {
        case 1:  return (int8_t)((const int*)src)[idx];
        case 2:  return (int8_t)(int)rintf(((const float*)src)[idx]);
        case 3:  return (int8_t)(int)rintf(__bfloat162float(((const __nv_bfloat16*)src)[idx]));
        default: return ((const int8_t*)src)[idx];
    }
}

// ---------------- weight prep (K-permuted s8) ----------------
__global__ void pack_w1_kernel(const void* __restrict__ gate_q, const void* __restrict__ up_q) {
    __shared__ int8_t tile[32][33];
    int wt = g_wtype;
    int e = blockIdx.z;
    int kbase = blockIdx.x * 32;
    int nbase = blockIdx.y * 32;
    int tx = threadIdx.x, ty = threadIdx.y;
    int p = nbase >> 6;
    int isup = (nbase >> 5) & 1;
    int colbase = p * 32;
    const void* src = isup ? up_q : gate_q;
#pragma unroll
    for (int j = 0; j < 4; j++) {
        int h = kbase + ty + 8 * j;
        tile[ty + 8 * j][tx] = load_w(src, ((size_t)e * HDIM + h) * IEDIM + colbase + tx, wt);
    }
    __syncthreads();
#pragma unroll
    for (int j = 0; j < 4; j++) {
        int n = nbase + ty + 8 * j;
        g_w1[((size_t)e * 512 + n) * HDIM + kperm(kbase + tx)] = tile[tx][ty + 8 * j];
    }
}

__global__ void transpose_down_kernel(const void* __restrict__ src) {
    __shared__ int8_t tile[32][33];
    int wt = g_wtype;
    int e = blockIdx.z;
    int cbase = blockIdx.x * 32;
    int rbase = blockIdx.y * 32;
    int tx = threadIdx.x, ty = threadIdx.y;
    size_t base = (size_t)e * IEDIM * HDIM;
#pragma unroll
    for (int j = 0; j < 4; j++) {
        int r = rbase + ty + 8 * j;
        tile[ty + 8 * j][tx] = load_w(src, base + (size_t)r * HDIM + cbase + tx, wt);
    }
    __syncthreads();
#pragma unroll
    for (int j = 0; j < 4; j++) {
        int c = cbase + ty + 8 * j;
        g_down_t[((size_t)e * HDIM + c) * IEDIM + kperm(rbase + tx)] = tile[tx][ty + 8 * j];
    }
}

// ---------------- activation quantize (shuffle-permuted s8) ----------------
__device__ __forceinline__ int clamp_qm(float v, float inv) {
    int a = (int)rintf(v * inv);
    return max(-128, min(127, a));
}
__device__ __forceinline__ unsigned perm_store_word(unsigned w, int lane) {
    unsigned pw = __shfl_xor_sync(0xffffffffu, w, 2);
    return (lane & 2) ? __byte_perm(pw, w, 0x7632) : __byte_perm(w, pw, 0x5410);
}
__device__ __forceinline__ int perm_store_idx(int j, int lane) {
    int q = ((lane & 1) << 1) | ((lane & 2) >> 1);
    return j * 32 + (lane & ~3) + q;
}

__global__ void quant_x_kernel(const float* __restrict__ x,
                               const int* __restrict__ token_ids,
                               const int* __restrict__ t2e, int T) {
    int w = threadIdx.x >> 5, lane = threadIdx.x & 31;
    int token = blockIdx.x * 8 + w;
    if (token >= T) return;
    const float4* row = (const float4*)(x + (size_t)token * HDIM);
    float4 v[8];
    float m = 0.f;
#pragma unroll
    for (int j = 0; j < 8; j++) {
        v[j] = row[j * 32 + lane];
        m = fmaxf(m, fmaxf(fmaxf(fabsf(v[j].x), fabsf(v[j].y)), fmaxf(fabsf(v[j].z), fabsf(v[j].w))));
    }
#pragma unroll
    for (int off = 16; off > 0; off >>= 1)
        m = fmaxf(m, __shfl_xor_sync(0xffffffffu, m, off));
    float scale = fmaxf(m / 127.0f, 1e-8f);
    float inv = 1.0f / scale;
    int* dst = (int*)(g_xq + (size_t)token * HDIM);
#pragma unroll
    for (int j = 0; j < 8; j++) {
        int a0 = clamp_qm(v[j].x, inv), a1 = clamp_qm(v[j].y, inv);
        int a2 = clamp_qm(v[j].z, inv), a3 = clamp_qm(v[j].w, inv);
        unsigned wq = (a0 & 0xff) | ((a1 & 0xff) << 8) | ((a2 & 0xff) << 16) | ((unsigned)a3 << 24);
        dst[perm_store_idx(j, lane)] = (int)perm_store_word(wq, lane);
    }
    if (lane == 0) {
        g_xs[token] = scale;
        int id = token_ids[token];
        id = min(max(id, 0), VOCAB - 1);
        int e = t2e[id];
        g_eid[token] = e;
        atomicAdd(&g_counts[e], 1);
    }
}

// scatter with local prefix (scan_kernel folded in)
__global__ void scatter_kernel(int T) {
    int offl[NEXP + 1];
    offl[0] = 0;
#pragma unroll
    for (int e = 0; e < NEXP; e++) offl[e + 1] = offl[e] + g_counts[e];
    int t = blockIdx.x * blockDim.x + threadIdx.x;
    if (blockIdx.x == 0 && threadIdx.x <= NEXP) g_off[threadIdx.x] = offl[threadIdx.x];
    if (t >= T) return;
    int e = g_eid[t];
    int pos = atomicAdd(&g_cursor[e], 1);
    g_perm[offl[e] + pos] = t;
}

__global__ void quant_i_kernel(int T) {
    int w = threadIdx.x >> 5, lane = threadIdx.x & 31;
    int token = blockIdx.x * 8 + w;
    if (token >= T) return;
    const float4* row = (const float4*)(g_inter + (size_t)token * IEDIM);
    float4 v[2];
    float m = 0.f;
#pragma unroll
    for (int j = 0; j < 2; j++) {
        v[j] = row[j * 32 + lane];
        m = fmaxf(m, fmaxf(fmaxf(fabsf(v[j].x), fabsf(v[j].y)), fmaxf(fabsf(v[j].z), fabsf(v[j].w))));
    }
#pragma unroll
    for (int off = 16; off > 0; off >>= 1)
        m = fmaxf(m, __shfl_xor_sync(0xffffffffu, m, off));
    float scale = fmaxf(m / 127.0f, 1e-8f);
    float inv = 1.0f / scale;
    int* dst = (int*)(g_iq + (size_t)token * IEDIM);
#pragma unroll
    for (int j = 0; j < 2; j++) {
        int a0 = clamp_qm(v[j].x, inv), a1 = clamp_qm(v[j].y, inv);
        int a2 = clamp_qm(v[j].z, inv), a3 = clamp_qm(v[j].w, inv);
        unsigned wq = (a0 & 0xff) | ((a1 & 0xff) << 8) | ((a2 & 0xff) << 16) | ((unsigned)a3 << 24);
        dst[perm_store_idx(j, lane)] = (int)perm_store_word(wq, lane);
    }
    if (lane == 0) g_is[token] = scale;
}

__device__ __forceinline__ bool map_tile(int bx, int& e, int& tile, int& cnt, int& off) {
    int acc = 0;
    for (int i = 0; i < NEXP; i++) {
        int c = g_off[i + 1] - g_off[i];
        int nt = (c + TILE_M - 1) >> 7;
        if (bx < acc + nt) { e = i; tile = bx - acc; cnt = c; off = g_off[i]; return true; }
        acc += nt;
    }
    return false;
}

__device__ __forceinline__ uint32_t tile_addr(uint32_t base_u32, int row, int kbyte) {
    return base_u32 + row * 128 + (((((kbyte) >> 4) & 7) ^ (row & 7)) << 4);
}

#define STG_A(stg) ((stg) * 16384)
#define STG_B(stg) (32768 + (stg) * 16384)
#define SMEM_GEMM 65536

#define SLICES_F16(aS, bS)                                                         \
    for (int ks = 0; ks < 8; ks++) {                                               \
        int kb = ks * 16;                                                          \
        unsigned af[2][4];                                                         \
        _Pragma("unroll")                                                          \
        for (int mt = 0; mt < 2; mt++) {                                           \
            unsigned r[2];                                                         \
            ldsm_x2(r, tile_addr(aS, wm * 32 + mt * 16 + rcA, kb));                \
            cvt4(r[0], af[mt][0], af[mt][2]);                                      \
            cvt4(r[1], af[mt][1], af[mt][3]);                                      \
        }                                                                          \
        unsigned bf[4][2][2];                                                      \
        _Pragma("unroll")                                                          \
        for (int p2 = 0; p2 < 4; p2++) {                                           \
            unsigned r[2];                                                         \
            ldsm_x2(r, tile_addr(bS, wn * 64 + p2 * 16 + rcA, kb));                \
            cvt4(r[0], bf[p2][0][0], bf[p2][0][1]);                                \
            cvt4(r[1], bf[p2][1][0], bf[p2][1][1]);                                \
        }                                                                          \
        _Pragma("unroll")                                                          \
        for (int mt = 0; mt < 2; mt++)                                             \
            _Pragma("unroll")                                                      \
            for (int nt = 0; nt < 8; nt++)                                         \
                mma_f16(c[mt][nt], af[mt], bf[nt >> 1][nt & 1]);                   \
    }

// ---------------- GEMM1 hybrid: y<2 HMMA (ch 0..127), y in {2,3} dp4a (ch 128..255) ----
__global__ __launch_bounds__(256, 2)
void gemm1_kernel(const float* __restrict__ gate_scale,
                  const float* __restrict__ up_scale) {
    extern __shared__ __align__(16) char smem[];

    int e, tile, cnt, off;
    if (!map_tile(blockIdx.x, e, tile, cnt, off)) return;
    int t = threadIdx.x;

    if (blockIdx.y >= 2) {
        // ---- dp4a branch (IDP pipe): 64 channels per CTA ----
        int j = blockIdx.y - 2;          // 0..1
        int cc = t & 63;
        int tg = t >> 6;                 // 0..3
        int pb = 4 + 2 * j + (cc >> 5);  // p-blocks 4..7
        int n_gate = pb * 64 + (cc & 31);
        const int4* wg_base = (const int4*)(g_w1 + ((size_t)e * 512 + n_gate) * HDIM);
        const int4* wu_base = wg_base + 32 * (HDIM / 16);   // +32 rows
        int ch = pb * 32 + (cc & 31);
        float gs = gate_scale[e * IEDIM + ch];
        float us = up_scale[e * IEDIM + ch];
        int4* srow = (int4*)smem;        // 32 tokens x 64 int4 = 32 KB

#pragma unroll 1
        for (int sp = 0; sp < 4; sp++) {
            __syncthreads();
#pragma unroll
            for (int i = 0; i < 8; i++) {
                int flat = t * 8 + i;
                int r = flat >> 6, chv = flat & 63;
                int m = tile * TILE_M + sp * 32 + r;
                int tok = g_perm[off + min(m, cnt - 1)];
                srow[flat] = ((const int4*)(g_xq + (size_t)tok * HDIM))[chv];
            }
            __syncthreads();
            int accg[8], accu[8];
#pragma unroll
            for (int i = 0; i < 8; i++) { accg[i] = 0; accu[i] = 0; }
#pragma unroll 1
            for (int kb = 0; kb < 8; kb++) {
                int4 wg[8], wu[8];
#pragma unroll
                for (int q = 0; q < 8; q++) { wg[q] = wg_base[kb * 8 + q]; wu[q] = wu_base[kb * 8 + q]; }
#pragma unroll
                for (int tk = 0; tk < 8; tk++) {
                    const int4* xr = srow + (tg * 8 + tk) * 64 + kb * 8;
#pragma unroll
                    for (int q = 0; q < 8; q++) {
                        int4 xv = xr[q];
                        accg[tk] = dp4a4(xv, wg[q], accg[tk]);
                        accu[tk] = dp4a4(xv, wu[q], accu[tk]);
                    }
                }
            }
#pragma unroll
            for (int tk = 0; tk < 8; tk++) {
                int m = tile * TILE_M + sp * 32 + tg * 8 + tk;
                if (m < cnt) {
                    int tok = g_perm[off + m];
                    float xs = g_xs[tok];
                    float gv = (float)accg[tk] * xs * gs;
                    float uv = (float)accu[tk] * xs * us;
                    g_inter[(size_t)tok * IEDIM + ch] = fast_silu_mul(gv, uv);
                }
            }
        }
        return;
    }

    // ---- f16/HMMA branch: P in {0,1}, channels 0..127 ----
    int P = blockIdx.y;
    int wid = t >> 5, lane = t & 31;
    int wm = wid & 3, wn = wid >> 2;
    int g = lane >> 2, tig = lane & 3;
    int rcA = (lane & 7) + ((lane & 8) ? 8 : 0);

    float c[2][8][4];
#pragma unroll
    for (int a = 0; a < 2; a++)
#pragma unroll
        for (int b = 0; b < 8; b++)
#pragma unroll
            for (int i = 0; i < 4; i++) c[a][b][i] = 0.f;

    int arow = t >> 1;
    int am = tile * TILE_M + arow;
    int atok = g_perm[off + min(am, cnt - 1)];
    const int4* asrc_base = (const int4*)(g_xq + (size_t)atok * HDIM);
    const int4* bsrc_base = (const int4*)(g_w1 + ((size_t)e * 512 + P * 128 + arow) * HDIM);
    int ch0 = (t & 1) * 4;
    uint32_t s_u32 = smem_u32(smem);

    auto load_stage = [&](int kc, int stg) {
        int4* da = (int4*)(smem + STG_A(stg) + arow * 128);
        const int4* ap = asrc_base + kc * 8;
#pragma unroll
        for (int ii = 0; ii < 4; ii++) { int ch = ch0 + ii; cp16(&da[ch ^ (arow & 7)], &ap[ch]); }
        int4* db = (int4*)(smem + STG_B(stg) + arow * 128);
        const int4* bp = bsrc_base + kc * 8;
#pragma unroll
        for (int ii = 0; ii < 4; ii++) { int ch = ch0 + ii; cp16(&db[ch ^ (arow & 7)], &bp[ch]); }
    };

    load_stage(0, 0);
    cp_commit();

    const int KC = HDIM / 128;    // 8
#pragma unroll 1
    for (int kc = 0; kc < KC; kc++) {
        if (kc + 1 < KC) {
            load_stage(kc + 1, (kc + 1) & 1);
            cp_commit();
            cp_wait<1>();
        } else {
            cp_wait<0>();
        }
        __syncthreads();
        uint32_t aS = s_u32 + STG_A(kc & 1);
        uint32_t bS = s_u32 + STG_B(kc & 1);
        SLICES_F16(aS, bS)
        __syncthreads();
    }

    int pb = 2 * P + wn;
    int chb = pb * 32;
    float gsv[8], usv[8];
#pragma unroll
    for (int nt = 0; nt < 4; nt++) {
        gsv[nt * 2]     = gate_scale[e * IEDIM + chb + nt * 8 + tig * 2];
        gsv[nt * 2 + 1] = gate_scale[e * IEDIM + chb + nt * 8 + tig * 2 + 1];
        usv[nt * 2]     = up_scale[e * IEDIM + chb + nt * 8 + tig * 2];
        usv[nt * 2 + 1] = up_scale[e * IEDIM + chb + nt * 8 + tig * 2 + 1];
    }
#pragma unroll
    for (int mt = 0; mt < 2; mt++) {
#pragma unroll
        for (int hh = 0; hh < 2; hh++) {
            int row = wm * 32 + mt * 16 + g + hh * 8;
            int m = tile * TILE_M + row;
            if (m >= cnt) continue;
            int tok = g_perm[off + m];
            float xs = g_xs[tok];
            float* obase = g_inter + (size_t)tok * IEDIM + chb;
#pragma unroll
            for (int nt = 0; nt < 4; nt++) {
                int i = hh * 2;
                float g0 = c[mt][nt][i]     * xs * gsv[nt * 2];
                float g1 = c[mt][nt][i + 1] * xs * gsv[nt * 2 + 1];
                float u0 = c[mt][nt + 4][i]     * xs * usv[nt * 2];
                float u1 = c[mt][nt + 4][i + 1] * xs * usv[nt * 2 + 1];
                *(float2*)(obase + nt * 8 + tig * 2) =
                    make_float2(fast_silu_mul(g0, u0), fast_silu_mul(g1, u1));
            }
        }
    }
}

// ---------------- GEMM2 hybrid: y<4 HMMA (cols 0..511), y in {4..11} dp4a (cols 512..1023) ----
__global__ __launch_bounds__(256, 2)
void gemm2_kernel(const float* __restrict__ down_scale, float* __restrict__ out) {
    extern __shared__ __align__(16) char smem[];

    int e, tile, cnt, off;
    if (!map_tile(blockIdx.x, e, tile, cnt, off)) return;
    int t = threadIdx.x;

    if (blockIdx.y >= 4) {
        // ---- dp4a branch: 64 output columns per CTA ----
        int j = blockIdx.y - 4;              // 0..7
        int col = 512 + j * 64 + (t & 63);
        int tg = t >> 6;                     // 0..3
        const int4* wd = (const int4*)(g_down_t + ((size_t)e * HDIM + col) * IEDIM);
        int4 w[16];
#pragma unroll
        for (int q = 0; q < 16; q++) w[q] = wd[q];
        float ds = down_scale[e * HDIM + col];
        int4* srow = (int4*)smem;            // 32 tokens x 16 int4 = 8 KB

#pragma unroll 1
        for (int sp = 0; sp < 4; sp++) {
            __syncthreads();
#pragma unroll
            for (int i = 0; i < 2; i++) {
                int flat = t * 2 + i;
                int r = flat >> 4, chv = flat & 15;
                int m = tile * TILE_M + sp * 32 + r;
                int tok = g_perm[off + min(m, cnt - 1)];
                srow[flat] = ((const int4*)(g_iq + (size_t)tok * IEDIM))[chv];
            }
            __syncthreads();
#pragma unroll
            for (int tk = 0; tk < 8; tk++) {
                const int4* xr = srow + (tg * 8 + tk) * 16;
                int acc = 0;
#pragma unroll
                for (int q = 0; q < 16; q++) acc = dp4a4(xr[q], w[q], acc);
                int m = tile * TILE_M + sp * 32 + tg * 8 + tk;
                if (m < cnt) {
                    int tok = g_perm[off + m];
                    out[(size_t)tok * HDIM + col] = (float)acc * g_is[tok] * ds;
                }
            }
        }
        return;
    }

    // ---- f16/HMMA branch: nb in 0..3, cols [nb*128, +128) ----
    int nb = blockIdx.y;
    int wid = t >> 5, lane = t & 31;
    int wm = wid & 3, wn = wid >> 2;
    int g = lane >> 2, tig = lane & 3;
    int rcA = (lane & 7) + ((lane & 8) ? 8 : 0);

    float c[2][8][4];
#pragma unroll
    for (int a = 0; a < 2; a++)
#pragma unroll
        for (int b = 0; b < 8; b++)
#pragma unroll
            for (int i = 0; i < 4; i++) c[a][b][i] = 0.f;

    int arow = t >> 1;
    int am = tile * TILE_M + arow;
    int atok = g_perm[off + min(am, cnt - 1)];
    const int4* asrc_base = (const int4*)(g_iq + (size_t)atok * IEDIM);
    const int4* bsrc_base = (const int4*)(g_down_t + ((size_t)e * HDIM + nb * 128 + arow) * IEDIM);
    int ch0 = (t & 1) * 4;
    uint32_t s_u32 = smem_u32(smem);

    auto load_stage = [&](int kc, int stg) {
        int4* da = (int4*)(smem + STG_A(stg) + arow * 128);
        const int4* ap = asrc_base + kc * 8;
#pragma unroll
        for (int ii = 0; ii < 4; ii++) { int ch = ch0 + ii; cp16(&da[ch ^ (arow & 7)], &ap[ch]); }
        int4* db = (int4*)(smem + STG_B(stg) + arow * 128);
        const int4* bp = bsrc_base + kc * 8;
#pragma unroll
        for (int ii = 0; ii < 4; ii++) { int ch = ch0 + ii; cp16(&db[ch ^ (arow & 7)], &bp[ch]); }
    };

    load_stage(0, 0);
    cp_commit();

    const int KC = IEDIM / 128;   // 2
#pragma unroll 1
    for (int kc = 0; kc < KC; kc++) {
        if (kc + 1 < KC) {
            load_stage(kc + 1, (kc + 1) & 1);
            cp_commit();
            cp_wait<1>();
        } else {
            cp_wait<0>();
        }
        __syncthreads();
        uint32_t aS = s_u32 + STG_A(kc & 1);
        uint32_t bS = s_u32 + STG_B(kc & 1);
        SLICES_F16(aS, bS)
        __syncthreads();
    }

    int colbase = nb * 128 + wn * 64;
    float dsv[16];
#pragma unroll
    for (int nt = 0; nt < 8; nt++) {
        dsv[nt * 2]     = down_scale[e * HDIM + colbase + nt * 8 + tig * 2];
        dsv[nt * 2 + 1] = down_scale[e * HDIM + colbase + nt * 8 + tig * 2 + 1];
    }
#pragma unroll
    for (int mt = 0; mt < 2; mt++) {
#pragma unroll
        for (int hh = 0; hh < 2; hh++) {
            int row = wm * 32 + mt * 16 + g + hh * 8;
            int m = tile * TILE_M + row;
            if (m >= cnt) continue;
            int tok = g_perm[off + m];
            float isv = g_is[tok];
            float* obase = out + (size_t)tok * HDIM + colbase;
#pragma unroll
            for (int nt = 0; nt < 8; nt++) {
                int i = hh * 2;
                float v0 = c[mt][nt][i]     * isv * dsv[nt * 2];
                float v1 = c[mt][nt][i + 1] * isv * dsv[nt * 2 + 1];
                *(float2*)(obase + nt * 8 + tig * 2) = make_float2(v0, v1);
            }
        }
    }
}

// ---------------- launch ----------------
extern "C" void kernel_launch(void* const* d_in, const int* in_sizes, int n_in,
                              void* d_out, int out_size) {
    const float* hidden      = (const float*)d_in[0];
    const int*   token_ids   = (const int*)d_in[1];
    const void*  gate_q      = d_in[2];
    const float* gate_scale  = (const float*)d_in[3];
    const void*  up_q        = d_in[4];
    const float* up_scale    = (const float*)d_in[5];
    const void*  down_q      = d_in[6];
    const float* down_scale  = (const float*)d_in[7];
    const int*   t2e         = (const int*)d_in[8];
    float* out = (float*)d_out;

    int T = in_sizes[0] / HDIM;     // 16384

    cudaFuncSetAttribute(gemm1_kernel, cudaFuncAttributeMaxDynamicSharedMemorySize, SMEM_GEMM);
    cudaFuncSetAttribute(gemm2_kernel, cudaFuncAttributeMaxDynamicSharedMemorySize, SMEM_GEMM);

    detect_reset_kernel<<<1, 256>>>(gate_q);

    {
        dim3 grid(HDIM / 32, 512 / 32, NEXP), blk(32, 8);
        pack_w1_kernel<<<grid, blk>>>(gate_q, up_q);
    }
    {
        dim3 grid(HDIM / 32, IEDIM / 32, NEXP), blk(32, 8);
        transpose_down_kernel<<<grid, blk>>>(down_q);
    }

    quant_x_kernel<<<(T + 7) / 8, 256>>>(hidden, token_ids, t2e, T);
    scatter_kernel<<<(T + 255) / 256, 256>>>(T);

    int ntiles = (T + TILE_M - 1) / TILE_M + NEXP;
    {
        dim3 grid(ntiles, 4);    // y 0..1 HMMA | y 2..3 dp4a
        gemm1_kernel<<<grid, 256, SMEM_GEMM>>>(gate_scale, up_scale);
    }
    quant_i_kernel<<<(T + 7) / 8, 256>>>(T);
    {
        dim3 grid(ntiles, 12);   // y 0..3 HMMA | y 4..11 dp4a
        gemm2_kernel<<<grid, 256, SMEM_GEMM>>>(down_scale, out);
    }
}

// round 16
// speedup vs baseline: 2.3083x; 2.3083x over previous
#include <cuda_runtime.h>
#include <cuda_bf16.h>
#include <cuda_fp16.h>
#include <cstdint>
#include <math.h>

#define HDIM 1024
#define IEDIM 256
#define NEXP 8
#define VOCAB 100000
#define TMAX 16384
#define TILE_M 128

// int8 tensors stored with each 16-byte K-group permuted:
// [x0 x1 x8 x9 | x2 x3 x10 x11 | x4 x5 x12 x13 | x6 x7 x14 x15]
// A and B share the permutation -> fragment pairings exact.
__device__ __align__(16) int8_t g_xq[TMAX * HDIM];
__device__ float  g_xs[TMAX];
__device__ __align__(16) int8_t g_iq[TMAX * IEDIM];
__device__ float  g_is[TMAX];
__device__ __align__(16) float  g_inter[TMAX * IEDIM];
__device__ __align__(16) int8_t g_w1[NEXP * 2 * IEDIM * HDIM]; // [e][512][1024]
__device__ __align__(16) int8_t g_down_t[NEXP * HDIM * IEDIM]; // [e][H][IE]
__device__ int g_eid[TMAX];
__device__ int g_perm[TMAX];
__device__ int g_counts[NEXP];
__device__ int g_cursor[NEXP];
__device__ int g_off[NEXP + 1];
__device__ int g_wtype;

__device__ __host__ __forceinline__ int kperm(int k) {
    int r = k & 15;
    int p = ((r & 7) >> 1) * 4 + ((r >> 3) << 1) + (r & 1);
    return (k & ~15) | p;
}

// ---------------- low-level helpers ----------------
__device__ __forceinline__ uint32_t smem_u32(const void* p) {
    return (uint32_t)__cvta_generic_to_shared(p);
}
__device__ __forceinline__ void cp16(void* s, const void* g) {
    asm volatile("cp.async.cg.shared.global [%0], [%1], 16;\n"
                 :: "r"(smem_u32(s)), "l"(g));
}
__device__ __forceinline__ void cp_commit() {
    asm volatile("cp.async.commit_group;\n");
}
template <int N>
__device__ __forceinline__ void cp_wait() {
    asm volatile("cp.async.wait_group %0;\n" :: "n"(N));
}
__device__ __forceinline__ void ldsm_x4(uint32_t* r, uint32_t addr) {
    asm volatile("ldmatrix.sync.aligned.m8n8.x4.shared.b16 {%0,%1,%2,%3}, [%4];"
                 : "=r"(r[0]), "=r"(r[1]), "=r"(r[2]), "=r"(r[3]) : "r"(addr));
}
__device__ __forceinline__ void mma_f16(float* c, const unsigned* a, const unsigned* b) {
    asm volatile(
        "mma.sync.aligned.m16n8k16.row.col.f32.f16.f16.f32 "
        "{%0,%1,%2,%3},{%4,%5,%6,%7},{%8,%9},{%0,%1,%2,%3};"
        : "+f"(c[0]), "+f"(c[1]), "+f"(c[2]), "+f"(c[3])
        : "r"(a[0]), "r"(a[1]), "r"(a[2]), "r"(a[3]), "r"(b[0]), "r"(b[1]));
}
__device__ __forceinline__ void cvt4(unsigned w, unsigned& lo, unsigned& hi) {
    unsigned t = w ^ 0x80808080u;
    unsigned l = __byte_perm(t, 0x64646464u, 0x5140);
    unsigned h = __byte_perm(t, 0x64646464u, 0x5342);
    unsigned bias = 0x64806480u;
    __half2 lh = __hsub2(*(__half2*)&l, *(__half2*)&bias);
    __half2 hh = __hsub2(*(__half2*)&h, *(__half2*)&bias);
    lo = *(unsigned*)&lh;
    hi = *(unsigned*)&hh;
}
__device__ __forceinline__ float fast_silu_mul(float gv, float uv) {
    float sig = __frcp_rn(1.0f + __expf(-gv));
    return gv * sig * uv;
}

// ---------------- dtype probe + counter reset ----------------
__global__ void detect_reset_kernel(const void* __restrict__ w) {
    int t = threadIdx.x;
    if (t < NEXP) { g_counts[t] = 0; g_cursor[t] = 0; }
    int iv = ((const int*)w)[t];
    bool ok_i32 = (iv >= -128 && iv <= 127);
    float fv = ((const float*)w)[t];
    bool ok_f32 = (fv == rintf(fv) && fabsf(fv) <= 127.0f);
    float bv = __bfloat162float(((const __nv_bfloat16*)w)[t]);
    bool ok_bf16 = (bv == rintf(bv) && fabsf(bv) <= 127.0f);
    int c1 = __syncthreads_count(ok_i32);
    int c2 = __syncthreads_count(ok_f32);
    int c3 = __syncthreads_count(ok_bf16);
    if (t == 0) {
        int wt = 0;
        if      (c1 >= 230) wt = 1;
        else if (c2 >= 230) wt = 2;
        else if (c3 >= 230) wt = 3;
        g_wtype = wt;
    }
}

__device__ __forceinline__ int8_t load_w(const void* __restrict__ src, size_t idx, int wt) {
    switch (wt) {
        case 1:  return (int8_t)((const int*)src)[idx];
        case 2:  return (int8_t)(int)rintf(((const float*)src)[idx]);
        case 3:  return (int8_t)(int)rintf(__bfloat162float(((const __nv_bfloat16*)src)[idx]));
        default: return ((const int8_t*)src)[idx];
    }
}

// ---------------- weight prep (K-permuted s8) ----------------
__global__ void pack_w1_kernel(const void* __restrict__ gate_q, const void* __restrict__ up_q) {
    __shared__ int8_t tile[32][33];
    int wt = g_wtype;
    int e = blockIdx.z;
    int kbase = blockIdx.x * 32;
    int nbase = blockIdx.y * 32;
    int tx = threadIdx.x, ty = threadIdx.y;
    int p = nbase >> 6;
    int isup = (nbase >> 5) & 1;
    int colbase = p * 32;
    const void* src = isup ? up_q : gate_q;
#pragma unroll
    for (int j = 0; j < 4; j++) {
        int h = kbase + ty + 8 * j;
        tile[ty + 8 * j][tx] = load_w(src, ((size_t)e * HDIM + h) * IEDIM + colbase + tx, wt);
    }
    __syncthreads();
#pragma unroll
    for (int j = 0; j < 4; j++) {
        int n = nbase + ty + 8 * j;
        g_w1[((size_t)e * 512 + n) * HDIM + kperm(kbase + tx)] = tile[tx][ty + 8 * j];
    }
}

__global__ void transpose_down_kernel(const void* __restrict__ src) {
    __shared__ int8_t tile[32][33];
    int wt = g_wtype;
    int e = blockIdx.z;
    int cbase = blockIdx.x * 32;
    int rbase = blockIdx.y * 32;
    int tx = threadIdx.x, ty = threadIdx.y;
    size_t base = (size_t)e * IEDIM * HDIM;
#pragma unroll
    for (int j = 0; j < 4; j++) {
        int r = rbase + ty + 8 * j;
        tile[ty + 8 * j][tx] = load_w(src, base + (size_t)r * HDIM + cbase + tx, wt);
    }
    __syncthreads();
#pragma unroll
    for (int j = 0; j < 4; j++) {
        int c = cbase + ty + 8 * j;
        g_down_t[((size_t)e * HDIM + c) * IEDIM + kperm(rbase + tx)] = tile[tx][ty + 8 * j];
    }
}

// ---------------- activation quantize (shuffle-permuted s8) ----------------
__device__ __forceinline__ int clamp_qm(float v, float inv) {
    int a = (int)rintf(v * inv);
    return max(-128, min(127, a));
}
__device__ __forceinline__ unsigned perm_store_word(unsigned w, int lane) {
    unsigned pw = __shfl_xor_sync(0xffffffffu, w, 2);
    return (lane & 2) ? __byte_perm(pw, w, 0x7632) : __byte_perm(w, pw, 0x5410);
}
__device__ __forceinline__ int perm_store_idx(int j, int lane) {
    int q = ((lane & 1) << 1) | ((lane & 2) >> 1);
    return j * 32 + (lane & ~3) + q;
}

// two-pass: max-pass (no buffering) then requant-pass (L1/L2 re-read) -> low regs, high occ
__global__ void quant_x_kernel(const float* __restrict__ x,
                               const int* __restrict__ token_ids,
                               const int* __restrict__ t2e, int T) {
    int w = threadIdx.x >> 5, lane = threadIdx.x & 31;
    int token = blockIdx.x * 8 + w;
    if (token >= T) return;
    const float4* row = (const float4*)(x + (size_t)token * HDIM);
    float m = 0.f;
#pragma unroll
    for (int j = 0; j < 8; j++) {
        float4 v = row[j * 32 + lane];
        m = fmaxf(m, fmaxf(fmaxf(fabsf(v.x), fabsf(v.y)), fmaxf(fabsf(v.z), fabsf(v.w))));
    }
#pragma unroll
    for (int off = 16; off > 0; off >>= 1)
        m = fmaxf(m, __shfl_xor_sync(0xffffffffu, m, off));
    float scale = fmaxf(m / 127.0f, 1e-8f);
    float inv = 1.0f / scale;
    int* dst = (int*)(g_xq + (size_t)token * HDIM);
#pragma unroll
    for (int j = 0; j < 8; j++) {
        float4 v = row[j * 32 + lane];
        int a0 = clamp_qm(v.x, inv), a1 = clamp_qm(v.y, inv);
        int a2 = clamp_qm(v.z, inv), a3 = clamp_qm(v.w, inv);
        unsigned wq = (a0 & 0xff) | ((a1 & 0xff) << 8) | ((a2 & 0xff) << 16) | ((unsigned)a3 << 24);
        dst[perm_store_idx(j, lane)] = (int)perm_store_word(wq, lane);
    }
    if (lane == 0) {
        g_xs[token] = scale;
        int id = token_ids[token];
        id = min(max(id, 0), VOCAB - 1);
        int e = t2e[id];
        g_eid[token] = e;
        atomicAdd(&g_counts[e], 1);
    }
}

// scatter with scan folded in (each block computes the 8-bin prefix locally)
__global__ void scatter_kernel(int T) {
    int offl[NEXP + 1];
    offl[0] = 0;
#pragma unroll
    for (int e = 0; e < NEXP; e++) offl[e + 1] = offl[e] + g_counts[e];
    if (blockIdx.x == 0 && threadIdx.x <= NEXP) g_off[threadIdx.x] = offl[threadIdx.x];
    int t = blockIdx.x * blockDim.x + threadIdx.x;
    if (t >= T) return;
    int e = g_eid[t];
    int pos = atomicAdd(&g_cursor[e], 1);
    g_perm[offl[e] + pos] = t;
}

__global__ void quant_i_kernel(int T) {
    int w = threadIdx.x >> 5, lane = threadIdx.x & 31;
    int token = blockIdx.x * 8 + w;
    if (token >= T) return;
    const float4* row = (const float4*)(g_inter + (size_t)token * IEDIM);
    float4 v[2];
    float m = 0.f;
#pragma unroll
    for (int j = 0; j < 2; j++) {
        v[j] = row[j * 32 + lane];
        m = fmaxf(m, fmaxf(fmaxf(fabsf(v[j].x), fabsf(v[j].y)), fmaxf(fabsf(v[j].z), fabsf(v[j].w))));
    }
#pragma unroll
    for (int off = 16; off > 0; off >>= 1)
        m = fmaxf(m, __shfl_xor_sync(0xffffffffu, m, off));
    float scale = fmaxf(m / 127.0f, 1e-8f);
    float inv = 1.0f / scale;
    int* dst = (int*)(g_iq + (size_t)token * IEDIM);
#pragma unroll
    for (int j = 0; j < 2; j++) {
        int a0 = clamp_qm(v[j].x, inv), a1 = clamp_qm(v[j].y, inv);
        int a2 = clamp_qm(v[j].z, inv), a3 = clamp_qm(v[j].w, inv);
        unsigned wq = (a0 & 0xff) | ((a1 & 0xff) << 8) | ((a2 & 0xff) << 16) | ((unsigned)a3 << 24);
        dst[perm_store_idx(j, lane)] = (int)perm_store_word(wq, lane);
    }
    if (lane == 0) g_is[token] = scale;
}

__device__ __forceinline__ bool map_tile(int bx, int& e, int& tile, int& cnt, int& off) {
    int acc = 0;
    for (int i = 0; i < NEXP; i++) {
        int c = g_off[i + 1] - g_off[i];
        int nt = (c + TILE_M - 1) >> 7;
        if (bx < acc + nt) { e = i; tile = bx - acc; cnt = c; off = g_off[i]; return true; }
        acc += nt;
    }
    return false;
}

__device__ __forceinline__ uint32_t tile_addr(uint32_t base_u32, int row, int kbyte) {
    return base_u32 + row * 128 + (((((kbyte) >> 4) & 7) ^ (row & 7)) << 4);
}

#define STG_A(stg) ((stg) * 16384)
#define STG_B(stg) (32768 + (stg) * 16384)
#define SMEM_GEMM 65536

// Double-slice inner loop: one ldsm_x4 fetches two k16 slices' fragments.
// Register mapping (validated bit-exact by R10's s8 path with identical addresses):
//  A (addr arA, kb+akA): reg0=rows0-7@kb, reg1=rows8-15@kb, reg2=rows0-7@kb+16, reg3=rows8-15@kb+16
//  B (addr brA, kb+bkA): reg0=cols0-7@kb, reg1=cols0-7@kb+16, reg2=cols8-15@kb, reg3=cols8-15@kb+16
#define SLICES_F16(aS, bS)                                                         \
    for (int ks2 = 0; ks2 < 4; ks2++) {                                            \
        int kb = ks2 * 32;                                                         \
        unsigned aw[2][4], bw[4][4];                                               \
        _Pragma("unroll")                                                          \
        for (int mt = 0; mt < 2; mt++)                                             \
            ldsm_x4(aw[mt], tile_addr(aS, wm * 32 + mt * 16 + arA, kb + akA));     \
        _Pragma("unroll")                                                          \
        for (int p2 = 0; p2 < 4; p2++)                                             \
            ldsm_x4(bw[p2], tile_addr(bS, wn * 64 + p2 * 16 + brA, kb + bkA));     \
        _Pragma("unroll")                                                          \
        for (int half = 0; half < 2; half++) {                                     \
            unsigned af[2][4];                                                     \
            _Pragma("unroll")                                                      \
            for (int mt = 0; mt < 2; mt++) {                                       \
                cvt4(aw[mt][half * 2],     af[mt][0], af[mt][2]);                  \
                cvt4(aw[mt][half * 2 + 1], af[mt][1], af[mt][3]);                  \
            }                                                                      \
            unsigned bf[4][2][2];                                                  \
            _Pragma("unroll")                                                      \
            for (int p2 = 0; p2 < 4; p2++) {                                       \
                cvt4(bw[p2][half],     bf[p2][0][0], bf[p2][0][1]);                \
                cvt4(bw[p2][2 + half], bf[p2][1][0], bf[p2][1][1]);                \
            }                                                                      \
            _Pragma("unroll")                                                      \
            for (int mt = 0; mt < 2; mt++)                                         \
                _Pragma("unroll")                                                  \
                for (int nt = 0; nt < 8; nt++)                                     \
                    mma_f16(c[mt][nt], af[mt], bf[nt >> 1][nt & 1]);               \
        }                                                                          \
    }

// ---------------- GEMM1: xq[128] @ W1[128 of 512 cols] -> g_inter ----------------
__global__ __launch_bounds__(256, 2)
void gemm1_kernel(const float* __restrict__ gate_scale,
                  const float* __restrict__ up_scale) {
    extern __shared__ __align__(16) char smem[];

    int e, tile, cnt, off;
    if (!map_tile(blockIdx.x, e, tile, cnt, off)) return;
    int P = blockIdx.y;              // 0..3

    int t = threadIdx.x;
    int wid = t >> 5, lane = t & 31;
    int wm = wid & 3, wn = wid >> 2;
    int g = lane >> 2, tig = lane & 3;
    int arA = (lane & 7) + ((lane & 8) ? 8 : 0);
    int akA = (lane & 16) ? 16 : 0;
    int brA = (lane & 7) + ((lane & 16) ? 8 : 0);
    int bkA = (lane & 8) ? 16 : 0;

    float c[2][8][4];
#pragma unroll
    for (int a = 0; a < 2; a++)
#pragma unroll
        for (int b = 0; b < 8; b++)
#pragma unroll
            for (int i = 0; i < 4; i++) c[a][b][i] = 0.f;

    int arow = t >> 1;
    int am = tile * TILE_M + arow;
    int atok = g_perm[off + min(am, cnt - 1)];
    const int4* asrc_base = (const int4*)(g_xq + (size_t)atok * HDIM);
    const int4* bsrc_base = (const int4*)(g_w1 + ((size_t)e * 512 + P * 128 + arow) * HDIM);
    int ch0 = (t & 1) * 4;
    uint32_t s_u32 = smem_u32(smem);

    auto load_stage = [&](int kc, int stg) {
        int4* da = (int4*)(smem + STG_A(stg) + arow * 128);
        const int4* ap = asrc_base + kc * 8;
#pragma unroll
        for (int ii = 0; ii < 4; ii++) { int ch = ch0 + ii; cp16(&da[ch ^ (arow & 7)], &ap[ch]); }
        int4* db = (int4*)(smem + STG_B(stg) + arow * 128);
        const int4* bp = bsrc_base + kc * 8;
#pragma unroll
        for (int ii = 0; ii < 4; ii++) { int ch = ch0 + ii; cp16(&db[ch ^ (arow & 7)], &bp[ch]); }
    };

    load_stage(0, 0);
    cp_commit();

    const int KC = HDIM / 128;    // 8
#pragma unroll 1
    for (int kc = 0; kc < KC; kc++) {
        if (kc + 1 < KC) {
            load_stage(kc + 1, (kc + 1) & 1);
            cp_commit();
            cp_wait<1>();
        } else {
            cp_wait<0>();
        }
        __syncthreads();
        uint32_t aS = s_u32 + STG_A(kc & 1);
        uint32_t bS = s_u32 + STG_B(kc & 1);
        SLICES_F16(aS, bS)
        __syncthreads();
    }

    // register-resident epilogue: warp's 64 cols = 32 gate (nt<4) + 32 up (nt>=4)
    int pb = 2 * P + wn;
    int chb = pb * 32;
    float gsv[8], usv[8];
#pragma unroll
    for (int nt = 0; nt < 4; nt++) {
        gsv[nt * 2]     = gate_scale[e * IEDIM + chb + nt * 8 + tig * 2];
        gsv[nt * 2 + 1] = gate_scale[e * IEDIM + chb + nt * 8 + tig * 2 + 1];
        usv[nt * 2]     = up_scale[e * IEDIM + chb + nt * 8 + tig * 2];
        usv[nt * 2 + 1] = up_scale[e * IEDIM + chb + nt * 8 + tig * 2 + 1];
    }
#pragma unroll
    for (int mt = 0; mt < 2; mt++) {
#pragma unroll
        for (int hh = 0; hh < 2; hh++) {
            int row = wm * 32 + mt * 16 + g + hh * 8;
            int m = tile * TILE_M + row;
            if (m >= cnt) continue;
            int tok = g_perm[off + m];
            float xs = g_xs[tok];
            float* obase = g_inter + (size_t)tok * IEDIM + chb;
#pragma unroll
            for (int nt = 0; nt < 4; nt++) {
                int i = hh * 2;
                float g0 = c[mt][nt][i]     * xs * gsv[nt * 2];
                float g1 = c[mt][nt][i + 1] * xs * gsv[nt * 2 + 1];
                float u0 = c[mt][nt + 4][i]     * xs * usv[nt * 2];
                float u1 = c[mt][nt + 4][i + 1] * xs * usv[nt * 2 + 1];
                *(float2*)(obase + nt * 8 + tig * 2) =
                    make_float2(fast_silu_mul(g0, u0), fast_silu_mul(g1, u1));
            }
        }
    }
}

// ---------------- GEMM2: iq[128] @ down[128 of 1024 cols] -> out ----------------
__global__ __launch_bounds__(256, 2)
void gemm2_kernel(const float* __restrict__ down_scale, float* __restrict__ out) {
    extern __shared__ __align__(16) char smem[];

    int e, tile, cnt, off;
    if (!map_tile(blockIdx.x, e, tile, cnt, off)) return;
    int nb = blockIdx.y;             // 0..7

    int t = threadIdx.x;
    int wid = t >> 5, lane = t & 31;
    int wm = wid & 3, wn = wid >> 2;
    int g = lane >> 2, tig = lane & 3;
    int arA = (lane & 7) + ((lane & 8) ? 8 : 0);
    int akA = (lane & 16) ? 16 : 0;
    int brA = (lane & 7) + ((lane & 16) ? 8 : 0);
    int bkA = (lane & 8) ? 16 : 0;

    float c[2][8][4];
#pragma unroll
    for (int a = 0; a < 2; a++)
#pragma unroll
        for (int b = 0; b < 8; b++)
#pragma unroll
            for (int i = 0; i < 4; i++) c[a][b][i] = 0.f;

    int arow = t >> 1;
    int am = tile * TILE_M + arow;
    int atok = g_perm[off + min(am, cnt - 1)];
    const int4* asrc_base = (const int4*)(g_iq + (size_t)atok * IEDIM);
    const int4* bsrc_base = (const int4*)(g_down_t + ((size_t)e * HDIM + nb * 128 + arow) * IEDIM);
    int ch0 = (t & 1) * 4;
    uint32_t s_u32 = smem_u32(smem);

    auto load_stage = [&](int kc, int stg) {
        int4* da = (int4*)(smem + STG_A(stg) + arow * 128);
        const int4* ap = asrc_base + kc * 8;
#pragma unroll
        for (int ii = 0; ii < 4; ii++) { int ch = ch0 + ii; cp16(&da[ch ^ (arow & 7)], &ap[ch]); }
        int4* db = (int4*)(smem + STG_B(stg) + arow * 128);
        const int4* bp = bsrc_base + kc * 8;
#pragma unroll
        for (int ii = 0; ii < 4; ii++) { int ch = ch0 + ii; cp16(&db[ch ^ (arow & 7)], &bp[ch]); }
    };

    load_stage(0, 0);
    cp_commit();

    const int KC = IEDIM / 128;   // 2
#pragma unroll 1
    for (int kc = 0; kc < KC; kc++) {
        if (kc + 1 < KC) {
            load_stage(kc + 1, (kc + 1) & 1);
            cp_commit();
            cp_wait<1>();
        } else {
            cp_wait<0>();
        }
        __syncthreads();
        uint32_t aS = s_u32 + STG_A(kc & 1);
        uint32_t bS = s_u32 + STG_B(kc & 1);
        SLICES_F16(aS, bS)
        __syncthreads();
    }

    int colbase = nb * 128 + wn * 64;
    float dsv[16];
#pragma unroll
    for (int nt = 0; nt < 8; nt++) {
        dsv[nt * 2]     = down_scale[e * HDIM + colbase + nt * 8 + tig * 2];
        dsv[nt * 2 + 1] = down_scale[e * HDIM + colbase + nt * 8 + tig * 2 + 1];
    }
#pragma unroll
    for (int mt = 0; mt < 2; mt++) {
#pragma unroll
        for (int hh = 0; hh < 2; hh++) {
            int row = wm * 32 + mt * 16 + g + hh * 8;
            int m = tile * TILE_M + row;
            if (m >= cnt) continue;
            int tok = g_perm[off + m];
            float isv = g_is[tok];
            float* obase = out + (size_t)tok * HDIM + colbase;
#pragma unroll
            for (int nt = 0; nt < 8; nt++) {
                int i = hh * 2;
                float v0 = c[mt][nt][i]     * isv * dsv[nt * 2];
                float v1 = c[mt][nt][i + 1] * isv * dsv[nt * 2 + 1];
                *(float2*)(obase + nt * 8 + tig * 2) = make_float2(v0, v1);
            }
        }
    }
}

// ---------------- launch ----------------
extern "C" void kernel_launch(void* const* d_in, const int* in_sizes, int n_in,
                              void* d_out, int out_size) {
    const float* hidden      = (const float*)d_in[0];
    const int*   token_ids   = (const int*)d_in[1];
    const void*  gate_q      = d_in[2];
    const float* gate_scale  = (const float*)d_in[3];
    const void*  up_q        = d_in[4];
    const float* up_scale    = (const float*)d_in[5];
    const void*  down_q      = d_in[6];
    const float* down_scale  = (const float*)d_in[7];
    const int*   t2e         = (const int*)d_in[8];
    float* out = (float*)d_out;

    int T = in_sizes[0] / HDIM;     // 16384

    cudaFuncSetAttribute(gemm1_kernel, cudaFuncAttributeMaxDynamicSharedMemorySize, SMEM_GEMM);
    cudaFuncSetAttribute(gemm2_kernel, cudaFuncAttributeMaxDynamicSharedMemorySize, SMEM_GEMM);

    detect_reset_kernel<<<1, 256>>>(gate_q);

    {
        dim3 grid(HDIM / 32, 512 / 32, NEXP), blk(32, 8);
        pack_w1_kernel<<<grid, blk>>>(gate_q, up_q);
    }
    {
        dim3 grid(HDIM / 32, IEDIM / 32, NEXP), blk(32, 8);
        transpose_down_kernel<<<grid, blk>>>(down_q);
    }

    quant_x_kernel<<<(T + 7) / 8, 256>>>(hidden, token_ids, t2e, T);
    scatter_kernel<<<(T + 255) / 256, 256>>>(T);

    int ntiles = (T + TILE_M - 1) / TILE_M + NEXP;
    {
        dim3 grid(ntiles, 4);
        gemm1_kernel<<<grid, 256, SMEM_GEMM>>>(gate_scale, up_scale);
    }
    quant_i_kernel<<<(T + 7) / 8, 256>>>(T);
    {
        dim3 grid(ntiles, 8);
        gemm2_kernel<<<grid, 256, SMEM_GEMM>>>(down_scale, out);
    }
}

// round 17
// speedup vs baseline: 2.3725x; 1.0278x over previous
#include <cuda_runtime.h>
#include <cuda_bf16.h>
#include <cuda_fp16.h>
#include <cstdint>
#include <math.h>

#define HDIM 1024
#define IEDIM 256
#define NEXP 8
#define VOCAB 100000
#define TMAX 16384
#define TILE_M 128

// int8 tensors stored with each 16-byte K-group permuted:
// [x0 x1 x8 x9 | x2 x3 x10 x11 | x4 x5 x12 x13 | x6 x7 x14 x15]
// A and B share the permutation -> fragment pairings exact.
__device__ __align__(16) int8_t g_xq[TMAX * HDIM];
__device__ float  g_xs[TMAX];
__device__ __align__(16) int8_t g_iq[TMAX * IEDIM];
__device__ float  g_is[TMAX];
__device__ __align__(16) float  g_inter[TMAX * IEDIM];
__device__ __align__(16) int8_t g_w1[NEXP * 2 * IEDIM * HDIM]; // [e][512][1024]
__device__ __align__(16) int8_t g_down_t[NEXP * HDIM * IEDIM]; // [e][H][IE]
__device__ int g_eid[TMAX];
__device__ int g_perm[TMAX];
__device__ int g_counts[NEXP];
__device__ int g_cursor[NEXP];
__device__ int g_off[NEXP + 1];
__device__ int g_wtype;

__device__ __host__ __forceinline__ int kperm(int k) {
    int r = k & 15;
    int p = ((r & 7) >> 1) * 4 + ((r >> 3) << 1) + (r & 1);
    return (k & ~15) | p;
}

// ---------------- low-level helpers ----------------
__device__ __forceinline__ uint32_t smem_u32(const void* p) {
    return (uint32_t)__cvta_generic_to_shared(p);
}
__device__ __forceinline__ void cp16(void* s, const void* g) {
    asm volatile("cp.async.cg.shared.global [%0], [%1], 16;\n"
                 :: "r"(smem_u32(s)), "l"(g));
}
__device__ __forceinline__ void cp_commit() {
    asm volatile("cp.async.commit_group;\n");
}
template <int N>
__device__ __forceinline__ void cp_wait() {
    asm volatile("cp.async.wait_group %0;\n" :: "n"(N));
}
__device__ __forceinline__ void ldsm_x4(uint32_t* r, uint32_t addr) {
    asm volatile("ldmatrix.sync.aligned.m8n8.x4.shared.b16 {%0,%1,%2,%3}, [%4];"
                 : "=r"(r[0]), "=r"(r[1]), "=r"(r[2]), "=r"(r[3]) : "r"(addr));
}
__device__ __forceinline__ void mma_f16(float* c, const unsigned* a, const unsigned* b) {
    asm volatile(
        "mma.sync.aligned.m16n8k16.row.col.f32.f16.f16.f32 "
        "{%0,%1,%2,%3},{%4,%5,%6,%7},{%8,%9},{%0,%1,%2,%3};"
        : "+f"(c[0]), "+f"(c[1]), "+f"(c[2]), "+f"(c[3])
        : "r"(a[0]), "r"(a[1]), "r"(a[2]), "r"(a[3]), "r"(b[0]), "r"(b[1]));
}
__device__ __forceinline__ void cvt4(unsigned w, unsigned& lo, unsigned& hi) {
    unsigned t = w ^ 0x80808080u;
    unsigned l = __byte_perm(t, 0x64646464u, 0x5140);
    unsigned h = __byte_perm(t, 0x64646464u, 0x5342);
    unsigned bias = 0x64806480u;
    __half2 lh = __hsub2(*(__half2*)&l, *(__half2*)&bias);
    __half2 hh = __hsub2(*(__half2*)&h, *(__half2*)&bias);
    lo = *(unsigned*)&lh;
    hi = *(unsigned*)&hh;
}
__device__ __forceinline__ float fast_silu_mul(float gv, float uv) {
    float sig = __frcp_rn(1.0f + __expf(-gv));
    return gv * sig * uv;
}

// ---------------- dtype probe + counter reset ----------------
__global__ void detect_reset_kernel(const void* __restrict__ w) {
    int t = threadIdx.x;
    if (t < NEXP) { g_counts[t] = 0; g_cursor[t] = 0; }
    int iv = ((const int*)w)[t];
    bool ok_i32 = (iv >= -128 && iv <= 127);
    float fv = ((const float*)w)[t];
    bool ok_f32 = (fv == rintf(fv) && fabsf(fv) <= 127.0f);
    float bv = __bfloat162float(((const __nv_bfloat16*)w)[t]);
    bool ok_bf16 = (bv == rintf(bv) && fabsf(bv) <= 127.0f);
    int c1 = __syncthreads_count(ok_i32);
    int c2 = __syncthreads_count(ok_f32);
    int c3 = __syncthreads_count(ok_bf16);
    if (t == 0) {
        int wt = 0;
        if      (c1 >= 230) wt = 1;
        else if (c2 >= 230) wt = 2;
        else if (c3 >= 230) wt = 3;
        g_wtype = wt;
    }
}

__device__ __forceinline__ int8_t load_w(const void* __restrict__ src, size_t idx, int wt) {
    switch (wt) {
        case 1:  return (int8_t)((const int*)src)[idx];
        case 2:  return (int8_t)(int)rintf(((const float*)src)[idx]);
        case 3:  return (int8_t)(int)rintf(__bfloat162float(((const __nv_bfloat16*)src)[idx]));
        default: return ((const int8_t*)src)[idx];
    }
}

// ---------------- weight prep (K-permuted s8) ----------------
__global__ void pack_w1_kernel(const void* __restrict__ gate_q, const void* __restrict__ up_q) {
    __shared__ int8_t tile[32][33];
    int wt = g_wtype;
    int e = blockIdx.z;
    int kbase = blockIdx.x * 32;
    int nbase = blockIdx.y * 32;
    int tx = threadIdx.x, ty = threadIdx.y;
    int p = nbase >> 6;
    int isup = (nbase >> 5) & 1;
    int colbase = p * 32;
    const void* src = isup ? up_q : gate_q;
#pragma unroll
    for (int j = 0; j < 4; j++) {
        int h = kbase + ty + 8 * j;
        tile[ty + 8 * j][tx] = load_w(src, ((size_t)e * HDIM + h) * IEDIM + colbase + tx, wt);
    }
    __syncthreads();
#pragma unroll
    for (int j = 0; j < 4; j++) {
        int n = nbase + ty + 8 * j;
        g_w1[((size_t)e * 512 + n) * HDIM + kperm(kbase + tx)] = tile[tx][ty + 8 * j];
    }
}

__global__ void transpose_down_kernel(const void* __restrict__ src) {
    __shared__ int8_t tile[32][33];
    int wt = g_wtype;
    int e = blockIdx.z;
    int cbase = blockIdx.x * 32;
    int rbase = blockIdx.y * 32;
    int tx = threadIdx.x, ty = threadIdx.y;
    size_t base = (size_t)e * IEDIM * HDIM;
#pragma unroll
    for (int j = 0; j < 4; j++) {
        int r = rbase + ty + 8 * j;
        tile[ty + 8 * j][tx] = load_w(src, base + (size_t)r * HDIM + cbase + tx, wt);
    }
    __syncthreads();
#pragma unroll
    for (int j = 0; j < 4; j++) {
        int c = cbase + ty + 8 * j;
        g_down_t[((size_t)e * HDIM + c) * IEDIM + kperm(rbase + tx)] = tile[tx][ty + 8 * j];
    }
}

// ---------------- activation quantize (shuffle-permuted s8) ----------------
__device__ __forceinline__ int clamp_qm(float v, float inv) {
    int a = (int)rintf(v * inv);
    return max(-128, min(127, a));
}
__device__ __forceinline__ unsigned perm_store_word(unsigned w, int lane) {
    unsigned pw = __shfl_xor_sync(0xffffffffu, w, 2);
    return (lane & 2) ? __byte_perm(pw, w, 0x7632) : __byte_perm(w, pw, 0x5410);
}
__device__ __forceinline__ int perm_store_idx(int j, int lane) {
    int q = ((lane & 1) << 1) | ((lane & 2) >> 1);
    return j * 32 + (lane & ~3) + q;
}

__global__ void quant_x_kernel(const float* __restrict__ x,
                               const int* __restrict__ token_ids,
                               const int* __restrict__ t2e, int T) {
    int w = threadIdx.x >> 5, lane = threadIdx.x & 31;
    int token = blockIdx.x * 8 + w;
    if (token >= T) return;
    const float4* row = (const float4*)(x + (size_t)token * HDIM);
    float m = 0.f;
#pragma unroll
    for (int j = 0; j < 8; j++) {
        float4 v = row[j * 32 + lane];
        m = fmaxf(m, fmaxf(fmaxf(fabsf(v.x), fabsf(v.y)), fmaxf(fabsf(v.z), fabsf(v.w))));
    }
#pragma unroll
    for (int off = 16; off > 0; off >>= 1)
        m = fmaxf(m, __shfl_xor_sync(0xffffffffu, m, off));
    float scale = fmaxf(m / 127.0f, 1e-8f);
    float inv = 1.0f / scale;
    int* dst = (int*)(g_xq + (size_t)token * HDIM);
#pragma unroll
    for (int j = 0; j < 8; j++) {
        float4 v = row[j * 32 + lane];
        int a0 = clamp_qm(v.x, inv), a1 = clamp_qm(v.y, inv);
        int a2 = clamp_qm(v.z, inv), a3 = clamp_qm(v.w, inv);
        unsigned wq = (a0 & 0xff) | ((a1 & 0xff) << 8) | ((a2 & 0xff) << 16) | ((unsigned)a3 << 24);
        dst[perm_store_idx(j, lane)] = (int)perm_store_word(wq, lane);
    }
    if (lane == 0) {
        g_xs[token] = scale;
        int id = token_ids[token];
        id = min(max(id, 0), VOCAB - 1);
        int e = t2e[id];
        g_eid[token] = e;
        atomicAdd(&g_counts[e], 1);
    }
}

// scatter with scan folded in
__global__ void scatter_kernel(int T) {
    int offl[NEXP + 1];
    offl[0] = 0;
#pragma unroll
    for (int e = 0; e < NEXP; e++) offl[e + 1] = offl[e] + g_counts[e];
    if (blockIdx.x == 0 && threadIdx.x <= NEXP) g_off[threadIdx.x] = offl[threadIdx.x];
    int t = blockIdx.x * blockDim.x + threadIdx.x;
    if (t >= T) return;
    int e = g_eid[t];
    int pos = atomicAdd(&g_cursor[e], 1);
    g_perm[offl[e] + pos] = t;
}

__global__ void quant_i_kernel(int T) {
    int w = threadIdx.x >> 5, lane = threadIdx.x & 31;
    int token = blockIdx.x * 8 + w;
    if (token >= T) return;
    const float4* row = (const float4*)(g_inter + (size_t)token * IEDIM);
    float4 v[2];
    float m = 0.f;
#pragma unroll
    for (int j = 0; j < 2; j++) {
        v[j] = row[j * 32 + lane];
        m = fmaxf(m, fmaxf(fmaxf(fabsf(v[j].x), fabsf(v[j].y)), fmaxf(fabsf(v[j].z), fabsf(v[j].w))));
    }
#pragma unroll
    for (int off = 16; off > 0; off >>= 1)
        m = fmaxf(m, __shfl_xor_sync(0xffffffffu, m, off));
    float scale = fmaxf(m / 127.0f, 1e-8f);
    float inv = 1.0f / scale;
    int* dst = (int*)(g_iq + (size_t)token * IEDIM);
#pragma unroll
    for (int j = 0; j < 2; j++) {
        int a0 = clamp_qm(v[j].x, inv), a1 = clamp_qm(v[j].y, inv);
        int a2 = clamp_qm(v[j].z, inv), a3 = clamp_qm(v[j].w, inv);
        unsigned wq = (a0 & 0xff) | ((a1 & 0xff) << 8) | ((a2 & 0xff) << 16) | ((unsigned)a3 << 24);
        dst[perm_store_idx(j, lane)] = (int)perm_store_word(wq, lane);
    }
    if (lane == 0) g_is[token] = scale;
}

__device__ __forceinline__ bool map_tile(int bx, int& e, int& tile, int& cnt, int& off) {
    int acc = 0;
    for (int i = 0; i < NEXP; i++) {
        int c = g_off[i + 1] - g_off[i];
        int nt = (c + TILE_M - 1) >> 7;
        if (bx < acc + nt) { e = i; tile = bx - acc; cnt = c; off = g_off[i]; return true; }
        acc += nt;
    }
    return false;
}

__device__ __forceinline__ uint32_t tile_addr(uint32_t base_u32, int row, int kbyte) {
    return base_u32 + row * 128 + (((((kbyte) >> 4) & 7) ^ (row & 7)) << 4);
}

// 3-stage pipeline: A stages then B stages
#define STG_A(stg) ((stg) * 16384)
#define STG_B(stg) (49152 + (stg) * 16384)
#define SMEM_GEMM 98304

// Double-slice inner loop (one ldsm_x4 = two k16 slices' raw bytes; cvt in regs)
#define SLICES_F16(aS, bS)                                                         \
    for (int ks2 = 0; ks2 < 4; ks2++) {                                            \
        int kb = ks2 * 32;                                                         \
        unsigned aw[2][4], bw[4][4];                                               \
        _Pragma("unroll")                                                          \
        for (int mt = 0; mt < 2; mt++)                                             \
            ldsm_x4(aw[mt], tile_addr(aS, wm * 32 + mt * 16 + arA, kb + akA));     \
        _Pragma("unroll")                                                          \
        for (int p2 = 0; p2 < 4; p2++)                                             \
            ldsm_x4(bw[p2], tile_addr(bS, wn * 64 + p2 * 16 + brA, kb + bkA));     \
        _Pragma("unroll")                                                          \
        for (int half = 0; half < 2; half++) {                                     \
            unsigned af[2][4];                                                     \
            _Pragma("unroll")                                                      \
            for (int mt = 0; mt < 2; mt++) {                                       \
                cvt4(aw[mt][half * 2],     af[mt][0], af[mt][2]);                  \
                cvt4(aw[mt][half * 2 + 1], af[mt][1], af[mt][3]);                  \
            }                                                                      \
            unsigned bf[4][2][2];                                                  \
            _Pragma("unroll")                                                      \
            for (int p2 = 0; p2 < 4; p2++) {                                       \
                cvt4(bw[p2][half],     bf[p2][0][0], bf[p2][0][1]);                \
                cvt4(bw[p2][2 + half], bf[p2][1][0], bf[p2][1][1]);                \
            }                                                                      \
            _Pragma("unroll")                                                      \
            for (int mt = 0; mt < 2; mt++)                                         \
                _Pragma("unroll")                                                  \
                for (int nt = 0; nt < 8; nt++)                                     \
                    mma_f16(c[mt][nt], af[mt], bf[nt >> 1][nt & 1]);               \
        }                                                                          \
    }

// ---------------- GEMM1: xq[128] @ W1[128 of 512 cols] -> g_inter ----------------
__global__ __launch_bounds__(256, 2)
void gemm1_kernel(const float* __restrict__ gate_scale,
                  const float* __restrict__ up_scale) {
    extern __shared__ __align__(16) char smem[];

    int e, tile, cnt, off;
    if (!map_tile(blockIdx.x, e, tile, cnt, off)) return;
    int P = blockIdx.y;              // 0..3

    int t = threadIdx.x;
    int wid = t >> 5, lane = t & 31;
    int wm = wid & 3, wn = wid >> 2;
    int g = lane >> 2, tig = lane & 3;
    int arA = (lane & 7) + ((lane & 8) ? 8 : 0);
    int akA = (lane & 16) ? 16 : 0;
    int brA = (lane & 7) + ((lane & 16) ? 8 : 0);
    int bkA = (lane & 8) ? 16 : 0;

    float c[2][8][4];
#pragma unroll
    for (int a = 0; a < 2; a++)
#pragma unroll
        for (int b = 0; b < 8; b++)
#pragma unroll
            for (int i = 0; i < 4; i++) c[a][b][i] = 0.f;

    int arow = t >> 1;
    int am = tile * TILE_M + arow;
    int atok = g_perm[off + min(am, cnt - 1)];
    const int4* asrc_base = (const int4*)(g_xq + (size_t)atok * HDIM);
    const int4* bsrc_base = (const int4*)(g_w1 + ((size_t)e * 512 + P * 128 + arow) * HDIM);
    int ch0 = (t & 1) * 4;
    uint32_t s_u32 = smem_u32(smem);

    auto load_stage = [&](int kc, int stg) {
        int4* da = (int4*)(smem + STG_A(stg) + arow * 128);
        const int4* ap = asrc_base + kc * 8;
#pragma unroll
        for (int ii = 0; ii < 4; ii++) { int ch = ch0 + ii; cp16(&da[ch ^ (arow & 7)], &ap[ch]); }
        int4* db = (int4*)(smem + STG_B(stg) + arow * 128);
        const int4* bp = bsrc_base + kc * 8;
#pragma unroll
        for (int ii = 0; ii < 4; ii++) { int ch = ch0 + ii; cp16(&db[ch ^ (arow & 7)], &bp[ch]); }
    };

    const int KC = HDIM / 128;    // 8
    load_stage(0, 0); cp_commit();
    load_stage(1, 1); cp_commit();

#pragma unroll 1
    for (int kc = 0; kc < KC; kc++) {
        if (kc + 1 < KC) { cp_wait<1>(); } else { cp_wait<0>(); }
        __syncthreads();
        int stg = kc % 3;
        uint32_t aS = s_u32 + STG_A(stg);
        uint32_t bS = s_u32 + STG_B(stg);
        SLICES_F16(aS, bS)
        if (kc + 2 < KC) { load_stage(kc + 2, (kc + 2) % 3); cp_commit(); }
    }

    // register-resident epilogue: warp's 64 cols = 32 gate (nt<4) + 32 up (nt>=4)
    int pb = 2 * P + wn;
    int chb = pb * 32;
    float gsv[8], usv[8];
#pragma unroll
    for (int nt = 0; nt < 4; nt++) {
        gsv[nt * 2]     = gate_scale[e * IEDIM + chb + nt * 8 + tig * 2];
        gsv[nt * 2 + 1] = gate_scale[e * IEDIM + chb + nt * 8 + tig * 2 + 1];
        usv[nt * 2]     = up_scale[e * IEDIM + chb + nt * 8 + tig * 2];
        usv[nt * 2 + 1] = up_scale[e * IEDIM + chb + nt * 8 + tig * 2 + 1];
    }
#pragma unroll
    for (int mt = 0; mt < 2; mt++) {
#pragma unroll
        for (int hh = 0; hh < 2; hh++) {
            int row = wm * 32 + mt * 16 + g + hh * 8;
            int m = tile * TILE_M + row;
            if (m >= cnt) continue;
            int tok = g_perm[off + m];
            float xs = g_xs[tok];
            float* obase = g_inter + (size_t)tok * IEDIM + chb;
#pragma unroll
            for (int nt = 0; nt < 4; nt++) {
                int i = hh * 2;
                float g0 = c[mt][nt][i]     * xs * gsv[nt * 2];
                float g1 = c[mt][nt][i + 1] * xs * gsv[nt * 2 + 1];
                float u0 = c[mt][nt + 4][i]     * xs * usv[nt * 2];
                float u1 = c[mt][nt + 4][i + 1] * xs * usv[nt * 2 + 1];
                *(float2*)(obase + nt * 8 + tig * 2) =
                    make_float2(fast_silu_mul(g0, u0), fast_silu_mul(g1, u1));
            }
        }
    }
}

// ---------------- GEMM2: iq[128] @ down[128 of 1024 cols] -> out ----------------
__global__ __launch_bounds__(256, 2)
void gemm2_kernel(const float* __restrict__ down_scale, float* __restrict__ out) {
    extern __shared__ __align__(16) char smem[];

    int e, tile, cnt, off;
    if (!map_tile(blockIdx.x, e, tile, cnt, off)) return;
    int nb = blockIdx.y;             // 0..7

    int t = threadIdx.x;
    int wid = t >> 5, lane = t & 31;
    int wm = wid & 3, wn = wid >> 2;
    int g = lane >> 2, tig = lane & 3;
    int arA = (lane & 7) + ((lane & 8) ? 8 : 0);
    int akA = (lane & 16) ? 16 : 0;
    int brA = (lane & 7) + ((lane & 16) ? 8 : 0);
    int bkA = (lane & 8) ? 16 : 0;

    float c[2][8][4];
#pragma unroll
    for (int a = 0; a < 2; a++)
#pragma unroll
        for (int b = 0; b < 8; b++)
#pragma unroll
            for (int i = 0; i < 4; i++) c[a][b][i] = 0.f;

    int arow = t >> 1;
    int am = tile * TILE_M + arow;
    int atok = g_perm[off + min(am, cnt - 1)];
    const int4* asrc_base = (const int4*)(g_iq + (size_t)atok * IEDIM);
    const int4* bsrc_base = (const int4*)(g_down_t + ((size_t)e * HDIM + nb * 128 + arow) * IEDIM);
    int ch0 = (t & 1) * 4;
    uint32_t s_u32 = smem_u32(smem);

    auto load_stage = [&](int kc, int stg) {
        int4* da = (int4*)(smem + STG_A(stg) + arow * 128);
        const int4* ap = asrc_base + kc * 8;
#pragma unroll
        for (int ii = 0; ii < 4; ii++) { int ch = ch0 + ii; cp16(&da[ch ^ (arow & 7)], &ap[ch]); }
        int4* db = (int4*)(smem + STG_B(stg) + arow * 128);
        const int4* bp = bsrc_base + kc * 8;
#pragma unroll
        for (int ii = 0; ii < 4; ii++) { int ch = ch0 + ii; cp16(&db[ch ^ (arow & 7)], &bp[ch]); }
    };

    const int KC = IEDIM / 128;   // 2
    load_stage(0, 0); cp_commit();
    load_stage(1, 1); cp_commit();

#pragma unroll 1
    for (int kc = 0; kc < KC; kc++) {
        if (kc + 1 < KC) { cp_wait<1>(); } else { cp_wait<0>(); }
        __syncthreads();
        int stg = kc % 3;
        uint32_t aS = s_u32 + STG_A(stg);
        uint32_t bS = s_u32 + STG_B(stg);
        SLICES_F16(aS, bS)
    }

    int colbase = nb * 128 + wn * 64;
    float dsv[16];
#pragma unroll
    for (int nt = 0; nt < 8; nt++) {
        dsv[nt * 2]     = down_scale[e * HDIM + colbase + nt * 8 + tig * 2];
        dsv[nt * 2 + 1] = down_scale[e * HDIM + colbase + nt * 8 + tig * 2 + 1];
    }
#pragma unroll
    for (int mt = 0; mt < 2; mt++) {
#pragma unroll
        for (int hh = 0; hh < 2; hh++) {
            int row = wm * 32 + mt * 16 + g + hh * 8;
            int m = tile * TILE_M + row;
            if (m >= cnt) continue;
            int tok = g_perm[off + m];
            float isv = g_is[tok];
            float* obase = out + (size_t)tok * HDIM + colbase;
#pragma unroll
            for (int nt = 0; nt < 8; nt++) {
                int i = hh * 2;
                float v0 = c[mt][nt][i]     * isv * dsv[nt * 2];
                float v1 = c[mt][nt][i + 1] * isv * dsv[nt * 2 + 1];
                *(float2*)(obase + nt * 8 + tig * 2) = make_float2(v0, v1);
            }
        }
    }
}

// ---------------- launch ----------------
extern "C" void kernel_launch(void* const* d_in, const int* in_sizes, int n_in,
                              void* d_out, int out_size) {
    const float* hidden      = (const float*)d_in[0];
    const int*   token_ids   = (const int*)d_in[1];
    const void*  gate_q      = d_in[2];
    const float* gate_scale  = (const float*)d_in[3];
    const void*  up_q        = d_in[4];
    const float* up_scale    = (const float*)d_in[5];
    const void*  down_q      = d_in[6];
    const float* down_scale  = (const float*)d_in[7];
    const int*   t2e         = (const int*)d_in[8];
    float* out = (float*)d_out;

    int T = in_sizes[0] / HDIM;     // 16384

    cudaFuncSetAttribute(gemm1_kernel, cudaFuncAttributeMaxDynamicSharedMemorySize, SMEM_GEMM);
    cudaFuncSetAttribute(gemm2_kernel, cudaFuncAttributeMaxDynamicSharedMemorySize, SMEM_GEMM);

    detect_reset_kernel<<<1, 256>>>(gate_q);

    {
        dim3 grid(HDIM / 32, 512 / 32, NEXP), blk(32, 8);
        pack_w1_kernel<<<grid, blk>>>(gate_q, up_q);
    }
    {
        dim3 grid(HDIM / 32, IEDIM / 32, NEXP), blk(32, 8);
        transpose_down_kernel<<<grid, blk>>>(down_q);
    }

    quant_x_kernel<<<(T + 7) / 8, 256>>>(hidden, token_ids, t2e, T);
    scatter_kernel<<<(T + 255) / 256, 256>>>(T);

    int ntiles = (T + TILE_M - 1) / TILE_M + NEXP;
    {
        dim3 grid(ntiles, 4);
        gemm1_kernel<<<grid, 256, SMEM_GEMM>>>(gate_scale, up_scale);
    }
    quant_i_kernel<<<(T + 7) / 8, 256>>>(T);
    {
        dim3 grid(ntiles, 8);
        gemm2_kernel<<<grid, 256, SMEM_GEMM>>>(down_scale, out);
    }
}